// round 2
// baseline (speedup 1.0000x reference)
#include <cuda_runtime.h>
#include <cub/cub.cuh>
#include <math.h>
#include <stdint.h>

#define NSCALE 2
#define NPTS   240000
#define NVOX   80000
#define NBATCH 2
#define NPB    120000
#define MPB    30000
#define HDIM   64
#define CDIM   20
#define MIDD   16
#define HIDD   128
#define NIMG   60000
#define CUBTEMP_BYTES (64u*1024u*1024u)

// ------------------------- static device scratch -------------------------
__device__ float g_H1[(size_t)NVOX * HIDD];       // hidden buffer (reused)
__device__ float g_pred3d[(size_t)NVOX * CDIM];
__device__ int   g_counts[(size_t)NVOX * CDIM];
__device__ int   g_voxlab[NVOX];
__device__ int   g_idx[NIMG];
__device__ float g_P[(size_t)NIMG * HDIM];
__device__ float g_a1[(size_t)NIMG * MIDD];
__device__ float g_a2[(size_t)NIMG * MIDD];
__device__ float g_attw[(size_t)NIMG * 2];
__device__ float g_y1[(size_t)NIMG * HDIM];
__device__ float g_y2[(size_t)NIMG * HDIM];
__device__ float g_feats[(size_t)NIMG * 2 * HDIM];
__device__ float g_fusepred[(size_t)NIMG * CDIM]; // also reused for img_logits
__device__ float g_stats[4 * HDIM];
__device__ unsigned long long g_keys_in[(size_t)CDIM * NVOX];
__device__ unsigned long long g_keys_out[(size_t)CDIM * NVOX];
__device__ unsigned char g_vals_in[(size_t)CDIM * NVOX];
__device__ unsigned char g_vals_out[(size_t)CDIM * NVOX];
__device__ int    g_gts[CDIM];
__device__ double g_classLoss[CDIM];
__device__ double g_loss;
__device__ unsigned char g_cubtemp[CUBTEMP_BYTES];

// ------------------------- reduction helper -------------------------
__device__ __forceinline__ double blockReduceSumD(double v) {
    __shared__ double sh[32];
    int lane = threadIdx.x & 31, wid = threadIdx.x >> 5;
#pragma unroll
    for (int o = 16; o > 0; o >>= 1) v += __shfl_down_sync(0xffffffffu, v, o);
    if (lane == 0) sh[wid] = v;
    __syncthreads();
    int nw = (blockDim.x + 31) >> 5;
    v = (threadIdx.x < nw) ? sh[threadIdx.x] : 0.0;
    if (wid == 0) {
#pragma unroll
        for (int o = 16; o > 0; o >>= 1) v += __shfl_down_sync(0xffffffffu, v, o);
    }
    return v;  // valid on thread 0
}

// ------------------------- elementwise kernels -------------------------
__global__ void k_idx(const int* __restrict__ coors_s, const int* __restrict__ p2img) {
    int r = blockIdx.x * blockDim.x + threadIdx.x;
    if (r < NIMG) {
        int b = r / MPB;
        int g = b * NPB + p2img[r];
        g_idx[r] = coors_s[g];
    }
}

__global__ void k_scatter(const int* __restrict__ coors_s, const int* __restrict__ labels) {
    int i = blockIdx.x * blockDim.x + threadIdx.x;
    if (i < NPTS) atomicAdd(&g_counts[(size_t)coors_s[i] * CDIM + labels[i]], 1);
}

__global__ void k_argmax() {
    int v = blockIdx.x * blockDim.x + threadIdx.x;
    if (v < NVOX) {
        const int* row = g_counts + (size_t)v * CDIM;
        int best = row[0], bi = 0;
#pragma unroll
        for (int c = 1; c < CDIM; c++) { int x = row[c]; if (x > best) { best = x; bi = c; } }
        g_voxlab[v] = bi;
    }
}

__global__ void k_gather(const float* __restrict__ pts_s) {
    int t = blockIdx.x * blockDim.x + threadIdx.x;
    if (t < NIMG * HDIM) {
        int r = t >> 6, c = t & 63;
        g_P[t] = pts_s[(size_t)g_idx[r] * HDIM + c];
    }
}

__global__ void k_att(const float* __restrict__ fc3w, const float* __restrict__ fc3b) {
    int r = blockIdx.x * blockDim.x + threadIdx.x;
    if (r >= NIMG) return;
    float z0 = fc3b[0], z1 = fc3b[1];
#pragma unroll
    for (int j = 0; j < MIDD; j++) {
        float v = g_a1[(size_t)r * MIDD + j];
        z0 += v * fc3w[j * 2 + 0];
        z1 += v * fc3w[j * 2 + 1];
    }
#pragma unroll
    for (int j = 0; j < MIDD; j++) {
        float v = g_a2[(size_t)r * MIDD + j];
        z0 += v * fc3w[(MIDD + j) * 2 + 0];
        z1 += v * fc3w[(MIDD + j) * 2 + 1];
    }
    g_attw[2 * r + 0] = 1.f / (1.f + expf(-z0));
    g_attw[2 * r + 1] = 1.f / (1.f + expf(-z1));
}

#define ROWSPB 512
__global__ void k_colstats(const float* __restrict__ y, int statsOff) {
    const int col = threadIdx.x & 63;
    const int grp = threadIdx.x >> 6;  // 0..3
    float s = 0.f, q = 0.f;
    int r0 = blockIdx.x * ROWSPB;
    int rend = r0 + ROWSPB; if (rend > NIMG) rend = NIMG;
    for (int r = r0 + grp; r < rend; r += 4) {
        float v = y[(size_t)r * HDIM + col];
        s += v; q += v * v;
    }
    __shared__ float sh[2][4][64];
    sh[0][grp][col] = s; sh[1][grp][col] = q;
    __syncthreads();
    if (grp == 0) {
        s = sh[0][0][col] + sh[0][1][col] + sh[0][2][col] + sh[0][3][col];
        q = sh[1][0][col] + sh[1][1][col] + sh[1][2][col] + sh[1][3][col];
        atomicAdd(&g_stats[statsOff + col], s);
        atomicAdd(&g_stats[statsOff + 64 + col], q);
    }
}

__global__ void k_fuse(const float* __restrict__ g1, const float* __restrict__ b1,
                       const float* __restrict__ g2, const float* __restrict__ b2, int s) {
    int t = blockIdx.x * blockDim.x + threadIdx.x;
    if (t >= NIMG * HDIM) return;
    int r = t >> 6, c = t & 63;
    const float n = (float)NIMG;
    float mu1 = g_stats[c] / n;        float var1 = g_stats[64 + c] / n - mu1 * mu1;
    float mu2 = g_stats[128 + c] / n;  float var2 = g_stats[192 + c] / n - mu2 * mu2;
    float v1 = fmaxf((g_y1[t] - mu1) * rsqrtf(var1 + 1e-5f) * g1[c] + b1[c], 0.f);
    float v2 = fmaxf((g_y2[t] - mu2) * rsqrtf(var2 + 1e-5f) * g2[c] + b2[c], 0.f);
    g_feats[(size_t)r * (2 * HDIM) + s * HDIM + c] = v1 * g_attw[2 * r] + v2 * g_attw[2 * r + 1];
}

// ------------------------- GEMM: C = act(A[M,K] @ W[K,N] + bias) -------------------------
template <bool RELU>
__global__ void __launch_bounds__(256) k_gemm(const float* __restrict__ A, int lda,
                                              const float* __restrict__ W,
                                              const float* __restrict__ bias,
                                              float* __restrict__ Cm,
                                              int M, int N, int K) {
    __shared__ __align__(16) float As[16][68];  // [k][m]
    __shared__ __align__(16) float Ws[16][68];  // [k][n]
    const int bm = blockIdx.y * 64, bn = blockIdx.x * 64;
    const int tid = threadIdx.x;
    const int tx = tid & 15, ty = tid >> 4;
    float acc[4][4] = {};
    for (int k0 = 0; k0 < K; k0 += 16) {
#pragma unroll
        for (int e = tid; e < 1024; e += 256) {
            int m = e >> 4, kk = e & 15;
            int gm = bm + m;
            As[kk][m] = (gm < M) ? A[(size_t)gm * lda + (k0 + kk)] : 0.f;
        }
#pragma unroll
        for (int e = tid; e < 1024; e += 256) {
            int kk = e >> 6, n2 = e & 63;
            int gn = bn + n2;
            Ws[kk][n2] = (gn < N) ? W[(size_t)(k0 + kk) * N + gn] : 0.f;
        }
        __syncthreads();
#pragma unroll
        for (int kk = 0; kk < 16; kk++) {
            float4 a4 = *(const float4*)&As[kk][ty * 4];
            float4 b4 = *(const float4*)&Ws[kk][tx * 4];
            float a[4] = {a4.x, a4.y, a4.z, a4.w};
            float b[4] = {b4.x, b4.y, b4.z, b4.w};
#pragma unroll
            for (int i = 0; i < 4; i++)
#pragma unroll
                for (int j = 0; j < 4; j++) acc[i][j] += a[i] * b[j];
        }
        __syncthreads();
    }
#pragma unroll
    for (int i = 0; i < 4; i++) {
        int gm = bm + ty * 4 + i;
        if (gm >= M) continue;
#pragma unroll
        for (int j = 0; j < 4; j++) {
            int gn = bn + tx * 4 + j;
            if (gn < N) {
                float v = acc[i][j] + bias[gn];
                if (RELU) v = fmaxf(v, 0.f);
                Cm[(size_t)gm * N + gn] = v;
            }
        }
    }
}

// ------------------------- loss kernels -------------------------
__global__ void k_hist(const int* __restrict__ lab, int n) {
    int i = blockIdx.x * blockDim.x + threadIdx.x;
    if (i < n) atomicAdd(&g_gts[lab[i]], 1);
}

// per row: softmax, CE contribution, and packed lovasz sort keys/values
__global__ void k_softmax_keys(const float* __restrict__ logits, const int* __restrict__ lab,
                               int n, float ce_w) {
    int i = blockIdx.x * blockDim.x + threadIdx.x;
    double ce = 0.0;
    if (i < n) {
        float z[CDIM];
#pragma unroll
        for (int c = 0; c < CDIM; c++) z[c] = logits[(size_t)i * CDIM + c];
        float m = z[0];
#pragma unroll
        for (int c = 1; c < CDIM; c++) m = fmaxf(m, z[c]);
        float se = 0.f;
#pragma unroll
        for (int c = 0; c < CDIM; c++) se += expf(z[c] - m);
        float ls = logf(se);
        int l = lab[i];
        ce = -(double)(z[l] - m - ls);
#pragma unroll
        for (int c = 0; c < CDIM; c++) {
            float p = expf(z[c] - m - ls);
            float fg = (c == l) ? 1.f : 0.f;
            float err = fabsf(fg - p);
            uint32_t eb = 0xFFFFFFFFu - __float_as_uint(err);
            g_keys_in[(size_t)c * n + i] = (((unsigned long long)c) << 32) | (unsigned long long)eb;
            g_vals_in[(size_t)c * n + i] = (unsigned char)(c == l);
        }
    }
    double tot = blockReduceSumD(ce);
    if (threadIdx.x == 0) atomicAdd(&g_loss, tot * (double)ce_w / (double)n);
}

// one block per class over its sorted segment
__global__ void __launch_bounds__(1024) k_lovasz(int n) {
    int c = blockIdx.x;
    int tid = threadIdx.x, lane = tid & 31, wid = tid >> 5;
    const unsigned long long* keys = g_keys_out + (size_t)c * n;
    const unsigned char* vals = g_vals_out + (size_t)c * n;
    float g = (float)g_gts[c];
    __shared__ int shWs[32];
    __shared__ double shD[32];
    int carry = 0;
    double acc = 0.0;
    for (int pos0 = 0; pos0 < n; pos0 += 1024) {
        int pos = pos0 + tid;
        int f = 0; float e = 0.f;
        if (pos < n) {
            unsigned long long k = keys[pos];
            f = (int)vals[pos];
            e = __uint_as_float(0xFFFFFFFFu - (uint32_t)(k & 0xFFFFFFFFull));
        }
        unsigned bal = __ballot_sync(0xffffffffu, f);
        int inclw = __popc(bal & (0xFFFFFFFFu >> (31 - lane)));
        if (lane == 31) shWs[wid] = inclw;
        __syncthreads();
        if (wid == 0) {
            int v = shWs[lane];
#pragma unroll
            for (int o = 1; o < 32; o <<= 1) {
                int u = __shfl_up_sync(0xffffffffu, v, o);
                if (lane >= o) v += u;
            }
            shWs[lane] = v;
        }
        __syncthreads();
        int cf = carry + inclw + (wid > 0 ? shWs[wid - 1] : 0);
        int total = shWs[31];
        if (pos < n) {
            float fi = (float)pos + 1.f;
            float cff = (float)cf;
            float jac = 1.f - (g - cff) / (g + fi - cff);
            float jacp = 0.f;
            if (pos > 0) {
                float cfp = cff - (float)f;
                jacp = 1.f - (g - cfp) / (g + (fi - 1.f) - cfp);
            }
            acc += (double)(e * (jac - jacp));
        }
        carry += total;
        __syncthreads();
    }
#pragma unroll
    for (int o = 16; o > 0; o >>= 1) acc += __shfl_down_sync(0xffffffffu, acc, o);
    if (lane == 0) shD[wid] = acc;
    __syncthreads();
    if (wid == 0) {
        double v = shD[lane];
#pragma unroll
        for (int o = 16; o > 0; o >>= 1) v += __shfl_down_sync(0xffffffffu, v, o);
        if (tid == 0) g_classLoss[c] = v;
    }
}

__global__ void k_lovreduce(float w) {
    int tid = threadIdx.x;
    double s = 0.0; int pc = 0;
    if (tid < CDIM && g_gts[tid] > 0) { s = g_classLoss[tid]; pc = 1; }
#pragma unroll
    for (int o = 16; o > 0; o >>= 1) {
        s += __shfl_down_sync(0xffffffffu, s, o);
        pc += __shfl_down_sync(0xffffffffu, pc, o);
    }
    if (tid == 0) {
        int d = pc > 0 ? pc : 1;
        atomicAdd(&g_loss, (double)w * s / (double)d);
    }
}

__global__ void k_kl(double w) {
    int r = blockIdx.x * blockDim.x + threadIdx.x;
    double local = 0.0;
    if (r < NIMG) {
        float zf[CDIM], zp[CDIM];
        int vi = g_idx[r];
#pragma unroll
        for (int c = 0; c < CDIM; c++) {
            zf[c] = g_fusepred[(size_t)r * CDIM + c];
            zp[c] = g_pred3d[(size_t)vi * CDIM + c];
        }
        float mf = zf[0], mp = zp[0];
#pragma unroll
        for (int c = 1; c < CDIM; c++) { mf = fmaxf(mf, zf[c]); mp = fmaxf(mp, zp[c]); }
        float sf = 0.f, sp = 0.f;
#pragma unroll
        for (int c = 0; c < CDIM; c++) { sf += expf(zf[c] - mf); sp += expf(zp[c] - mp); }
        float lsf = logf(sf), lsp = logf(sp);
        float acc = 0.f;
#pragma unroll
        for (int c = 0; c < CDIM; c++) {
            float lp = zf[c] - mf - lsf;
            float p = expf(lp);
            float lq = zp[c] - mp - lsp;
            acc += p * (lp - lq);
        }
        local = (double)acc;
    }
    double tot = blockReduceSumD(local);
    if (threadIdx.x == 0) atomicAdd(&g_loss, tot * w);
}

__global__ void k_finish(float* out) { out[0] = (float)g_loss; }

// ------------------------- host -------------------------
static inline int ceildiv(int a, int b) { return (a + b - 1) / b; }

extern "C" void kernel_launch(void* const* d_in, const int* in_sizes, int n_in,
                              void* d_out, int out_size) {
    const float* img_feat = (const float*)d_in[0];
    const float* pts_feat = (const float*)d_in[1];
    const int*   coors_inv = (const int*)d_in[2];
    const int*   labels   = (const int*)d_in[3];
    const int*   img_label = (const int*)d_in[4];
    const int*   p2img    = (const int*)d_in[5];
    const float* w3a = (const float*)d_in[6];  const float* b3a = (const float*)d_in[7];
    const float* w3b = (const float*)d_in[8];  const float* b3b = (const float*)d_in[9];
    const float* wfa = (const float*)d_in[10]; const float* bfa = (const float*)d_in[11];
    const float* wfb = (const float*)d_in[12]; const float* bfb = (const float*)d_in[13];
    const float* fc1w = (const float*)d_in[14]; const float* fc1b = (const float*)d_in[15];
    const float* fc2w = (const float*)d_in[16]; const float* fc2b = (const float*)d_in[17];
    const float* fc3w = (const float*)d_in[18]; const float* fc3b = (const float*)d_in[19];
    const float* c1w = (const float*)d_in[20]; const float* c1b = (const float*)d_in[21];
    const float* bn1g = (const float*)d_in[22]; const float* bn1b = (const float*)d_in[23];
    const float* c2w = (const float*)d_in[24]; const float* c2b = (const float*)d_in[25];
    const float* bn2g = (const float*)d_in[26]; const float* bn2b = (const float*)d_in[27];
    const float* clw1 = (const float*)d_in[28]; const float* clb1 = (const float*)d_in[29];
    const float* clw2 = (const float*)d_in[30]; const float* clb2 = (const float*)d_in[31];

    void *p_loss, *p_counts, *p_stats, *p_gts, *p_kin, *p_kout, *p_vin, *p_vout, *p_temp;
    void *p_H1, *p_pred, *p_P, *p_a1, *p_a2, *p_y1, *p_y2, *p_feats, *p_fpred, *p_voxlab;
    cudaGetSymbolAddress(&p_loss, g_loss);
    cudaGetSymbolAddress(&p_counts, g_counts);
    cudaGetSymbolAddress(&p_stats, g_stats);
    cudaGetSymbolAddress(&p_gts, g_gts);
    cudaGetSymbolAddress(&p_kin, g_keys_in);
    cudaGetSymbolAddress(&p_kout, g_keys_out);
    cudaGetSymbolAddress(&p_vin, g_vals_in);
    cudaGetSymbolAddress(&p_vout, g_vals_out);
    cudaGetSymbolAddress(&p_temp, g_cubtemp);
    cudaGetSymbolAddress(&p_H1, g_H1);
    cudaGetSymbolAddress(&p_pred, g_pred3d);
    cudaGetSymbolAddress(&p_P, g_P);
    cudaGetSymbolAddress(&p_a1, g_a1);
    cudaGetSymbolAddress(&p_a2, g_a2);
    cudaGetSymbolAddress(&p_y1, g_y1);
    cudaGetSymbolAddress(&p_y2, g_y2);
    cudaGetSymbolAddress(&p_feats, g_feats);
    cudaGetSymbolAddress(&p_fpred, g_fusepred);
    cudaGetSymbolAddress(&p_voxlab, g_voxlab);

    float* H1 = (float*)p_H1;    float* pred = (float*)p_pred;
    float* P = (float*)p_P;      float* a1 = (float*)p_a1;   float* a2 = (float*)p_a2;
    float* y1 = (float*)p_y1;    float* y2 = (float*)p_y2;
    float* feats = (float*)p_feats; float* fpred = (float*)p_fpred;
    const int* voxlab = (const int*)p_voxlab;

    cudaStream_t st = 0;
    cudaMemsetAsync(p_loss, 0, sizeof(double), st);

    auto run_lovasz = [&](int n, float weight) {
        size_t tb = CUBTEMP_BYTES;
        cub::DeviceRadixSort::SortPairs(
            p_temp, tb,
            (const unsigned long long*)p_kin, (unsigned long long*)p_kout,
            (const unsigned char*)p_vin, (unsigned char*)p_vout,
            CDIM * n, 0, 37, st);
        k_lovasz<<<CDIM, 1024, 0, st>>>(n);
        k_lovreduce<<<1, 32, 0, st>>>(weight);
    };
    auto gemm_grid = [](int M, int N) { return dim3((unsigned)ceildiv(N, 64), (unsigned)ceildiv(M, 64)); };

    for (int s = 0; s < NSCALE; s++) {
        const float* pts_s = pts_feat + (size_t)s * NVOX * HDIM;
        const float* img_s = img_feat + (size_t)s * NIMG * HDIM;
        const int* coors_s = coors_inv + (size_t)s * NPTS;

        // 3D classifier: pred3d = relu(pts @ w3a + b3a) @ w3b + b3b
        k_gemm<true><<<gemm_grid(NVOX, HIDD), 256, 0, st>>>(
            pts_s, HDIM, w3a + (size_t)s * HDIM * HIDD, b3a + s * HIDD, H1, NVOX, HIDD, HDIM);
        k_gemm<false><<<gemm_grid(NVOX, CDIM), 256, 0, st>>>(
            H1, HIDD, w3b + (size_t)s * HIDD * CDIM, b3b + s * CDIM, pred, NVOX, CDIM, HIDD);

        // voxel majority vote
        cudaMemsetAsync(p_counts, 0, (size_t)NVOX * CDIM * sizeof(int), st);
        k_scatter<<<ceildiv(NPTS, 256), 256, 0, st>>>(coors_s, labels);
        k_argmax<<<ceildiv(NVOX, 256), 256, 0, st>>>();

        // seg_loss(pred3d, vox_lab)
        cudaMemsetAsync(p_gts, 0, CDIM * sizeof(int), st);
        k_hist<<<ceildiv(NVOX, 256), 256, 0, st>>>(voxlab, NVOX);
        k_softmax_keys<<<ceildiv(NVOX, 256), 256, 0, st>>>(pred, voxlab, NVOX, 1.0f);
        run_lovasz(NVOX, 1.0f);

        // fusion path
        k_idx<<<ceildiv(NIMG, 256), 256, 0, st>>>(coors_s, p2img);
        k_gather<<<ceildiv(NIMG * HDIM, 256), 256, 0, st>>>(pts_s);
        k_gemm<false><<<gemm_grid(NIMG, MIDD), 256, 0, st>>>(
            P, HDIM, fc1w + (size_t)s * HDIM * MIDD, fc1b + s * MIDD, a1, NIMG, MIDD, HDIM);
        k_gemm<false><<<gemm_grid(NIMG, MIDD), 256, 0, st>>>(
            img_s, HDIM, fc2w + (size_t)s * HDIM * MIDD, fc2b + s * MIDD, a2, NIMG, MIDD, HDIM);
        k_att<<<ceildiv(NIMG, 256), 256, 0, st>>>(fc3w + (size_t)s * 2 * MIDD * 2, fc3b + s * 2);
        k_gemm<false><<<gemm_grid(NIMG, HDIM), 256, 0, st>>>(
            P, HDIM, c1w + (size_t)s * HDIM * HDIM, c1b + s * HDIM, y1, NIMG, HDIM, HDIM);
        k_gemm<false><<<gemm_grid(NIMG, HDIM), 256, 0, st>>>(
            img_s, HDIM, c2w + (size_t)s * HDIM * HDIM, c2b + s * HDIM, y2, NIMG, HDIM, HDIM);
        cudaMemsetAsync(p_stats, 0, 4 * HDIM * sizeof(float), st);
        k_colstats<<<ceildiv(NIMG, ROWSPB), 256, 0, st>>>(y1, 0);
        k_colstats<<<ceildiv(NIMG, ROWSPB), 256, 0, st>>>(y2, 128);
        k_fuse<<<ceildiv(NIMG * HDIM, 256), 256, 0, st>>>(
            bn1g + s * HDIM, bn1b + s * HDIM, bn2g + s * HDIM, bn2b + s * HDIM, s);

        // fuse classifier
        k_gemm<true><<<gemm_grid(NIMG, HIDD), 256, 0, st>>>(
            feats + s * HDIM, 2 * HDIM, wfa + (size_t)s * HDIM * HIDD, bfa + s * HIDD,
            H1, NIMG, HIDD, HDIM);
        k_gemm<false><<<gemm_grid(NIMG, CDIM), 256, 0, st>>>(
            H1, HIDD, wfb + (size_t)s * HIDD * CDIM, bfb + s * CDIM, fpred, NIMG, CDIM, HIDD);

        // seg_loss(fuse_pred, img_label) * 0.5
        cudaMemsetAsync(p_gts, 0, CDIM * sizeof(int), st);
        k_hist<<<ceildiv(NIMG, 256), 256, 0, st>>>(img_label, NIMG);
        k_softmax_keys<<<ceildiv(NIMG, 256), 256, 0, st>>>(fpred, img_label, NIMG, 0.5f);
        run_lovasz(NIMG, 0.5f);

        // KL * 0.05/2 (mean over NIMG*C elements)
        k_kl<<<ceildiv(NIMG, 256), 256, 0, st>>>(0.025 / ((double)NIMG * (double)CDIM));
    }

    // final classifier on concatenated feats
    k_gemm<true><<<gemm_grid(NIMG, HIDD), 256, 0, st>>>(
        feats, 2 * HDIM, clw1, clb1, H1, NIMG, HIDD, 2 * HDIM);
    k_gemm<false><<<gemm_grid(NIMG, CDIM), 256, 0, st>>>(
        H1, HIDD, clw2, clb2, fpred, NIMG, CDIM, HIDD);
    cudaMemsetAsync(p_gts, 0, CDIM * sizeof(int), st);
    k_hist<<<ceildiv(NIMG, 256), 256, 0, st>>>(img_label, NIMG);
    k_softmax_keys<<<ceildiv(NIMG, 256), 256, 0, st>>>(fpred, img_label, NIMG, 1.0f);
    run_lovasz(NIMG, 1.0f);

    k_finish<<<1, 1, 0, st>>>((float*)d_out);
}

// round 3
// speedup vs baseline: 1.1613x; 1.1613x over previous
#include <cuda_runtime.h>
#include <cub/cub.cuh>
#include <math.h>
#include <stdint.h>

#define NSCALE 2
#define NPTS   240000
#define NVOX   80000
#define NBATCH 2
#define NPB    120000
#define MPB    30000
#define HDIM   64
#define CDIM   20
#define MIDD   16
#define HIDD   128
#define NIMG   60000
#define CUBTEMP_BYTES (64u*1024u*1024u)

// ------------------------- static device scratch -------------------------
__device__ float g_H1[(size_t)NVOX * HIDD];       // hidden buffer (reused)
__device__ float g_pred3d[(size_t)NVOX * CDIM];
__device__ int   g_counts[(size_t)NVOX * CDIM];
__device__ int   g_voxlab[NVOX];
__device__ int   g_idx[NIMG];
__device__ float g_P[(size_t)NIMG * HDIM];
__device__ float g_a1[(size_t)NIMG * MIDD];
__device__ float g_a2[(size_t)NIMG * MIDD];
__device__ float g_attw[(size_t)NIMG * 2];
__device__ float g_y1[(size_t)NIMG * HDIM];
__device__ float g_y2[(size_t)NIMG * HDIM];
__device__ float g_feats[(size_t)NIMG * 2 * HDIM];
__device__ float g_fusepred[(size_t)NIMG * CDIM]; // also reused for img_logits
__device__ float g_stats[4 * HDIM];
__device__ uint32_t g_keys_in[(size_t)CDIM * NVOX];
__device__ uint32_t g_keys_out[(size_t)CDIM * NVOX];
__device__ int    g_gts[CDIM];
__device__ double g_classLoss[CDIM];
__device__ double g_loss;
__device__ unsigned char g_cubtemp[CUBTEMP_BYTES];

// ------------------------- reduction helper -------------------------
__device__ __forceinline__ double blockReduceSumD(double v) {
    __shared__ double sh[32];
    int lane = threadIdx.x & 31, wid = threadIdx.x >> 5;
#pragma unroll
    for (int o = 16; o > 0; o >>= 1) v += __shfl_down_sync(0xffffffffu, v, o);
    if (lane == 0) sh[wid] = v;
    __syncthreads();
    int nw = (blockDim.x + 31) >> 5;
    v = (threadIdx.x < nw) ? sh[threadIdx.x] : 0.0;
    if (wid == 0) {
#pragma unroll
        for (int o = 16; o > 0; o >>= 1) v += __shfl_down_sync(0xffffffffu, v, o);
    }
    return v;  // valid on thread 0
}

// ------------------------- elementwise kernels -------------------------
__global__ void k_idx(const int* __restrict__ coors_s, const int* __restrict__ p2img) {
    int r = blockIdx.x * blockDim.x + threadIdx.x;
    if (r < NIMG) {
        int b = r / MPB;
        int g = b * NPB + p2img[r];
        g_idx[r] = coors_s[g];
    }
}

__global__ void k_scatter(const int* __restrict__ coors_s, const int* __restrict__ labels) {
    int i = blockIdx.x * blockDim.x + threadIdx.x;
    if (i < NPTS) atomicAdd(&g_counts[(size_t)coors_s[i] * CDIM + labels[i]], 1);
}

__global__ void k_argmax() {
    int v = blockIdx.x * blockDim.x + threadIdx.x;
    if (v < NVOX) {
        const int* row = g_counts + (size_t)v * CDIM;
        int best = row[0], bi = 0;
#pragma unroll
        for (int c = 1; c < CDIM; c++) { int x = row[c]; if (x > best) { best = x; bi = c; } }
        g_voxlab[v] = bi;
    }
}

__global__ void k_gather(const float* __restrict__ pts_s) {
    int t = blockIdx.x * blockDim.x + threadIdx.x;
    if (t < NIMG * HDIM) {
        int r = t >> 6, c = t & 63;
        g_P[t] = pts_s[(size_t)g_idx[r] * HDIM + c];
    }
}

__global__ void k_att(const float* __restrict__ fc3w, const float* __restrict__ fc3b) {
    int r = blockIdx.x * blockDim.x + threadIdx.x;
    if (r >= NIMG) return;
    float z0 = fc3b[0], z1 = fc3b[1];
#pragma unroll
    for (int j = 0; j < MIDD; j++) {
        float v = g_a1[(size_t)r * MIDD + j];
        z0 += v * fc3w[j * 2 + 0];
        z1 += v * fc3w[j * 2 + 1];
    }
#pragma unroll
    for (int j = 0; j < MIDD; j++) {
        float v = g_a2[(size_t)r * MIDD + j];
        z0 += v * fc3w[(MIDD + j) * 2 + 0];
        z1 += v * fc3w[(MIDD + j) * 2 + 1];
    }
    g_attw[2 * r + 0] = 1.f / (1.f + expf(-z0));
    g_attw[2 * r + 1] = 1.f / (1.f + expf(-z1));
}

#define ROWSPB 512
__global__ void k_colstats(const float* __restrict__ y, int statsOff) {
    const int col = threadIdx.x & 63;
    const int grp = threadIdx.x >> 6;  // 0..3
    float s = 0.f, q = 0.f;
    int r0 = blockIdx.x * ROWSPB;
    int rend = r0 + ROWSPB; if (rend > NIMG) rend = NIMG;
    for (int r = r0 + grp; r < rend; r += 4) {
        float v = y[(size_t)r * HDIM + col];
        s += v; q += v * v;
    }
    __shared__ float sh[2][4][64];
    sh[0][grp][col] = s; sh[1][grp][col] = q;
    __syncthreads();
    if (grp == 0) {
        s = sh[0][0][col] + sh[0][1][col] + sh[0][2][col] + sh[0][3][col];
        q = sh[1][0][col] + sh[1][1][col] + sh[1][2][col] + sh[1][3][col];
        atomicAdd(&g_stats[statsOff + col], s);
        atomicAdd(&g_stats[statsOff + 64 + col], q);
    }
}

__global__ void k_fuse(const float* __restrict__ g1, const float* __restrict__ b1,
                       const float* __restrict__ g2, const float* __restrict__ b2, int s) {
    int t = blockIdx.x * blockDim.x + threadIdx.x;
    if (t >= NIMG * HDIM) return;
    int r = t >> 6, c = t & 63;
    const float n = (float)NIMG;
    float mu1 = g_stats[c] / n;        float var1 = g_stats[64 + c] / n - mu1 * mu1;
    float mu2 = g_stats[128 + c] / n;  float var2 = g_stats[192 + c] / n - mu2 * mu2;
    float v1 = fmaxf((g_y1[t] - mu1) * rsqrtf(var1 + 1e-5f) * g1[c] + b1[c], 0.f);
    float v2 = fmaxf((g_y2[t] - mu2) * rsqrtf(var2 + 1e-5f) * g2[c] + b2[c], 0.f);
    g_feats[(size_t)r * (2 * HDIM) + s * HDIM + c] = v1 * g_attw[2 * r] + v2 * g_attw[2 * r + 1];
}

// ------------------------- GEMM: C = act(A[M,K] @ W[K,N] + bias) -------------------------
// templated tile: BM x BN block tile, TM x TN per-thread micro-tile, 256 threads.
template <int BM, int BN, int TM, int TN, bool RELU>
__global__ void __launch_bounds__(256) k_gemm(const float* __restrict__ A, int lda,
                                              const float* __restrict__ W,
                                              const float* __restrict__ bias,
                                              float* __restrict__ Cm,
                                              int M, int N, int K) {
    constexpr int TX = BN / TN;
    constexpr int TY = BM / TM;
    static_assert(TX * TY == 256, "bad tile");
    __shared__ __align__(16) float As[16][BM + 4];
    __shared__ __align__(16) float Ws[16][BN + 4];
    const int bm = blockIdx.y * BM, bn = blockIdx.x * BN;
    const int tid = threadIdx.x;
    const int tx = tid % TX, ty = tid / TX;
    float acc[TM][TN] = {};
    for (int k0 = 0; k0 < K; k0 += 16) {
#pragma unroll
        for (int e = tid; e < BM * 16; e += 256) {
            int m = e >> 4, kk = e & 15;
            int gm = bm + m;
            As[kk][m] = (gm < M) ? A[(size_t)gm * lda + (k0 + kk)] : 0.f;
        }
#pragma unroll
        for (int e = tid; e < BN * 16; e += 256) {
            int kk = e / BN, n2 = e % BN;
            int gn = bn + n2;
            Ws[kk][n2] = (gn < N) ? W[(size_t)(k0 + kk) * N + gn] : 0.f;
        }
        __syncthreads();
#pragma unroll
        for (int kk = 0; kk < 16; kk++) {
            float a[TM], b[TN];
#pragma unroll
            for (int i = 0; i < TM; i++) a[i] = As[kk][ty * TM + i];
#pragma unroll
            for (int j = 0; j < TN; j++) b[j] = Ws[kk][tx * TN + j];
#pragma unroll
            for (int i = 0; i < TM; i++)
#pragma unroll
                for (int j = 0; j < TN; j++) acc[i][j] += a[i] * b[j];
        }
        __syncthreads();
    }
#pragma unroll
    for (int i = 0; i < TM; i++) {
        int gm = bm + ty * TM + i;
        if (gm >= M) continue;
#pragma unroll
        for (int j = 0; j < TN; j++) {
            int gn = bn + tx * TN + j;
            if (gn < N) {
                float v = acc[i][j] + bias[gn];
                if (RELU) v = fmaxf(v, 0.f);
                Cm[(size_t)gm * N + gn] = v;
            }
        }
    }
}

// ------------------------- loss kernels -------------------------
__global__ void k_hist(const int* __restrict__ lab, int n) {
    int i = blockIdx.x * blockDim.x + threadIdx.x;
    if (i < n) atomicAdd(&g_gts[lab[i]], 1);
}

// per row: softmax, CE contribution, packed 32-bit lovasz sort keys
// key = (c << 26) | ((0x3F800000 - err_bits) >> 5 << 1) | fg   (31 bits)
__global__ void k_softmax_keys(const float* __restrict__ logits, const int* __restrict__ lab,
                               int n, float ce_w) {
    int i = blockIdx.x * blockDim.x + threadIdx.x;
    double ce = 0.0;
    if (i < n) {
        float z[CDIM];
#pragma unroll
        for (int c = 0; c < CDIM; c++) z[c] = logits[(size_t)i * CDIM + c];
        float m = z[0];
#pragma unroll
        for (int c = 1; c < CDIM; c++) m = fmaxf(m, z[c]);
        float se = 0.f;
#pragma unroll
        for (int c = 0; c < CDIM; c++) se += expf(z[c] - m);
        float ls = logf(se);
        int l = lab[i];
        ce = -(double)(z[l] - m - ls);
#pragma unroll
        for (int c = 0; c < CDIM; c++) {
            float p = expf(z[c] - m - ls);
            uint32_t fg = (c == l) ? 1u : 0u;
            float err = fabsf((float)fg - p);
            uint32_t desc = 0x3F800000u - __float_as_uint(err);
            uint32_t key = ((uint32_t)c << 26) | (((desc >> 5) << 1) | fg);
            g_keys_in[(size_t)c * n + i] = key;
        }
    }
    double tot = blockReduceSumD(ce);
    if (threadIdx.x == 0) atomicAdd(&g_loss, tot * (double)ce_w / (double)n);
}

// one block per class over its sorted segment
__global__ void __launch_bounds__(1024) k_lovasz(int n) {
    int c = blockIdx.x;
    int tid = threadIdx.x, lane = tid & 31, wid = tid >> 5;
    const uint32_t* keys = g_keys_out + (size_t)c * n;
    float g = (float)g_gts[c];
    __shared__ int shWs[32];
    __shared__ double shD[32];
    int carry = 0;
    double acc = 0.0;
    for (int pos0 = 0; pos0 < n; pos0 += 1024) {
        int pos = pos0 + tid;
        int f = 0; float e = 0.f;
        if (pos < n) {
            uint32_t k = keys[pos];
            f = (int)(k & 1u);
            uint32_t desc = (k >> 1) & 0x1FFFFFFu;
            e = __uint_as_float(0x3F800000u - (desc << 5));
        }
        unsigned bal = __ballot_sync(0xffffffffu, f);
        int inclw = __popc(bal & (0xFFFFFFFFu >> (31 - lane)));
        if (lane == 31) shWs[wid] = inclw;
        __syncthreads();
        if (wid == 0) {
            int v = shWs[lane];
#pragma unroll
            for (int o = 1; o < 32; o <<= 1) {
                int u = __shfl_up_sync(0xffffffffu, v, o);
                if (lane >= o) v += u;
            }
            shWs[lane] = v;
        }
        __syncthreads();
        int cf = carry + inclw + (wid > 0 ? shWs[wid - 1] : 0);
        int total = shWs[31];
        if (pos < n) {
            float fi = (float)pos + 1.f;
            float cff = (float)cf;
            float jac = 1.f - (g - cff) / (g + fi - cff);
            float jacp = 0.f;
            if (pos > 0) {
                float cfp = cff - (float)f;
                jacp = 1.f - (g - cfp) / (g + (fi - 1.f) - cfp);
            }
            acc += (double)(e * (jac - jacp));
        }
        carry += total;
        __syncthreads();
    }
#pragma unroll
    for (int o = 16; o > 0; o >>= 1) acc += __shfl_down_sync(0xffffffffu, acc, o);
    if (lane == 0) shD[wid] = acc;
    __syncthreads();
    if (wid == 0) {
        double v = shD[lane];
#pragma unroll
        for (int o = 16; o > 0; o >>= 1) v += __shfl_down_sync(0xffffffffu, v, o);
        if (tid == 0) g_classLoss[c] = v;
    }
}

__global__ void k_lovreduce(float w) {
    int tid = threadIdx.x;
    double s = 0.0; int pc = 0;
    if (tid < CDIM && g_gts[tid] > 0) { s = g_classLoss[tid]; pc = 1; }
#pragma unroll
    for (int o = 16; o > 0; o >>= 1) {
        s += __shfl_down_sync(0xffffffffu, s, o);
        pc += __shfl_down_sync(0xffffffffu, pc, o);
    }
    if (tid == 0) {
        int d = pc > 0 ? pc : 1;
        atomicAdd(&g_loss, (double)w * s / (double)d);
    }
}

__global__ void k_kl(double w) {
    int r = blockIdx.x * blockDim.x + threadIdx.x;
    double local = 0.0;
    if (r < NIMG) {
        float zf[CDIM], zp[CDIM];
        int vi = g_idx[r];
#pragma unroll
        for (int c = 0; c < CDIM; c++) {
            zf[c] = g_fusepred[(size_t)r * CDIM + c];
            zp[c] = g_pred3d[(size_t)vi * CDIM + c];
        }
        float mf = zf[0], mp = zp[0];
#pragma unroll
        for (int c = 1; c < CDIM; c++) { mf = fmaxf(mf, zf[c]); mp = fmaxf(mp, zp[c]); }
        float sf = 0.f, sp = 0.f;
#pragma unroll
        for (int c = 0; c < CDIM; c++) { sf += expf(zf[c] - mf); sp += expf(zp[c] - mp); }
        float lsf = logf(sf), lsp = logf(sp);
        float acc = 0.f;
#pragma unroll
        for (int c = 0; c < CDIM; c++) {
            float lp = zf[c] - mf - lsf;
            float p = expf(lp);
            float lq = zp[c] - mp - lsp;
            acc += p * (lp - lq);
        }
        local = (double)acc;
    }
    double tot = blockReduceSumD(local);
    if (threadIdx.x == 0) atomicAdd(&g_loss, tot * w);
}

__global__ void k_finish(float* out) { out[0] = (float)g_loss; }

// ------------------------- host -------------------------
static inline int ceildiv(int a, int b) { return (a + b - 1) / b; }

extern "C" void kernel_launch(void* const* d_in, const int* in_sizes, int n_in,
                              void* d_out, int out_size) {
    const float* img_feat = (const float*)d_in[0];
    const float* pts_feat = (const float*)d_in[1];
    const int*   coors_inv = (const int*)d_in[2];
    const int*   labels   = (const int*)d_in[3];
    const int*   img_label = (const int*)d_in[4];
    const int*   p2img    = (const int*)d_in[5];
    const float* w3a = (const float*)d_in[6];  const float* b3a = (const float*)d_in[7];
    const float* w3b = (const float*)d_in[8];  const float* b3b = (const float*)d_in[9];
    const float* wfa = (const float*)d_in[10]; const float* bfa = (const float*)d_in[11];
    const float* wfb = (const float*)d_in[12]; const float* bfb = (const float*)d_in[13];
    const float* fc1w = (const float*)d_in[14]; const float* fc1b = (const float*)d_in[15];
    const float* fc2w = (const float*)d_in[16]; const float* fc2b = (const float*)d_in[17];
    const float* fc3w = (const float*)d_in[18]; const float* fc3b = (const float*)d_in[19];
    const float* c1w = (const float*)d_in[20]; const float* c1b = (const float*)d_in[21];
    const float* bn1g = (const float*)d_in[22]; const float* bn1b = (const float*)d_in[23];
    const float* c2w = (const float*)d_in[24]; const float* c2b = (const float*)d_in[25];
    const float* bn2g = (const float*)d_in[26]; const float* bn2b = (const float*)d_in[27];
    const float* clw1 = (const float*)d_in[28]; const float* clb1 = (const float*)d_in[29];
    const float* clw2 = (const float*)d_in[30]; const float* clb2 = (const float*)d_in[31];

    void *p_loss, *p_counts, *p_stats, *p_gts, *p_kin, *p_kout, *p_temp;
    void *p_H1, *p_pred, *p_P, *p_a1, *p_a2, *p_y1, *p_y2, *p_feats, *p_fpred, *p_voxlab;
    cudaGetSymbolAddress(&p_loss, g_loss);
    cudaGetSymbolAddress(&p_counts, g_counts);
    cudaGetSymbolAddress(&p_stats, g_stats);
    cudaGetSymbolAddress(&p_gts, g_gts);
    cudaGetSymbolAddress(&p_kin, g_keys_in);
    cudaGetSymbolAddress(&p_kout, g_keys_out);
    cudaGetSymbolAddress(&p_temp, g_cubtemp);
    cudaGetSymbolAddress(&p_H1, g_H1);
    cudaGetSymbolAddress(&p_pred, g_pred3d);
    cudaGetSymbolAddress(&p_P, g_P);
    cudaGetSymbolAddress(&p_a1, g_a1);
    cudaGetSymbolAddress(&p_a2, g_a2);
    cudaGetSymbolAddress(&p_y1, g_y1);
    cudaGetSymbolAddress(&p_y2, g_y2);
    cudaGetSymbolAddress(&p_feats, g_feats);
    cudaGetSymbolAddress(&p_fpred, g_fusepred);
    cudaGetSymbolAddress(&p_voxlab, g_voxlab);

    float* H1 = (float*)p_H1;    float* pred = (float*)p_pred;
    float* P = (float*)p_P;      float* a1 = (float*)p_a1;   float* a2 = (float*)p_a2;
    float* y1 = (float*)p_y1;    float* y2 = (float*)p_y2;
    float* feats = (float*)p_feats; float* fpred = (float*)p_fpred;
    const int* voxlab = (const int*)p_voxlab;

    cudaStream_t st = 0;
    cudaMemsetAsync(p_loss, 0, sizeof(double), st);

    auto run_lovasz = [&](int n, float weight) {
        size_t tb = CUBTEMP_BYTES;
        cub::DeviceRadixSort::SortKeys(
            p_temp, tb,
            (const uint32_t*)p_kin, (uint32_t*)p_kout,
            CDIM * n, 0, 31, st);
        k_lovasz<<<CDIM, 1024, 0, st>>>(n);
        k_lovreduce<<<1, 32, 0, st>>>(weight);
    };
    // big tile: 128x64 block, 8x4 micro
    auto grid_big = [](int M, int N) { return dim3((unsigned)ceildiv(N, 64), (unsigned)ceildiv(M, 128)); };
    // small-N tile: 64x32 block, 4x2 micro
    auto grid_small = [](int M, int N) { return dim3((unsigned)ceildiv(N, 32), (unsigned)ceildiv(M, 64)); };

    for (int s = 0; s < NSCALE; s++) {
        const float* pts_s = pts_feat + (size_t)s * NVOX * HDIM;
        const float* img_s = img_feat + (size_t)s * NIMG * HDIM;
        const int* coors_s = coors_inv + (size_t)s * NPTS;

        // 3D classifier: pred3d = relu(pts @ w3a + b3a) @ w3b + b3b
        k_gemm<128, 64, 8, 4, true><<<grid_big(NVOX, HIDD), 256, 0, st>>>(
            pts_s, HDIM, w3a + (size_t)s * HDIM * HIDD, b3a + s * HIDD, H1, NVOX, HIDD, HDIM);
        k_gemm<64, 32, 4, 2, false><<<grid_small(NVOX, CDIM), 256, 0, st>>>(
            H1, HIDD, w3b + (size_t)s * HIDD * CDIM, b3b + s * CDIM, pred, NVOX, CDIM, HIDD);

        // voxel majority vote
        cudaMemsetAsync(p_counts, 0, (size_t)NVOX * CDIM * sizeof(int), st);
        k_scatter<<<ceildiv(NPTS, 256), 256, 0, st>>>(coors_s, labels);
        k_argmax<<<ceildiv(NVOX, 256), 256, 0, st>>>();

        // seg_loss(pred3d, vox_lab)
        cudaMemsetAsync(p_gts, 0, CDIM * sizeof(int), st);
        k_hist<<<ceildiv(NVOX, 256), 256, 0, st>>>(voxlab, NVOX);
        k_softmax_keys<<<ceildiv(NVOX, 256), 256, 0, st>>>(pred, voxlab, NVOX, 1.0f);
        run_lovasz(NVOX, 1.0f);

        // fusion path
        k_idx<<<ceildiv(NIMG, 256), 256, 0, st>>>(coors_s, p2img);
        k_gather<<<ceildiv(NIMG * HDIM, 256), 256, 0, st>>>(pts_s);
        k_gemm<64, 32, 4, 2, false><<<grid_small(NIMG, MIDD), 256, 0, st>>>(
            P, HDIM, fc1w + (size_t)s * HDIM * MIDD, fc1b + s * MIDD, a1, NIMG, MIDD, HDIM);
        k_gemm<64, 32, 4, 2, false><<<grid_small(NIMG, MIDD), 256, 0, st>>>(
            img_s, HDIM, fc2w + (size_t)s * HDIM * MIDD, fc2b + s * MIDD, a2, NIMG, MIDD, HDIM);
        k_att<<<ceildiv(NIMG, 256), 256, 0, st>>>(fc3w + (size_t)s * 2 * MIDD * 2, fc3b + s * 2);
        k_gemm<128, 64, 8, 4, false><<<grid_big(NIMG, HDIM), 256, 0, st>>>(
            P, HDIM, c1w + (size_t)s * HDIM * HDIM, c1b + s * HDIM, y1, NIMG, HDIM, HDIM);
        k_gemm<128, 64, 8, 4, false><<<grid_big(NIMG, HDIM), 256, 0, st>>>(
            img_s, HDIM, c2w + (size_t)s * HDIM * HDIM, c2b + s * HDIM, y2, NIMG, HDIM, HDIM);
        cudaMemsetAsync(p_stats, 0, 4 * HDIM * sizeof(float), st);
        k_colstats<<<ceildiv(NIMG, ROWSPB), 256, 0, st>>>(y1, 0);
        k_colstats<<<ceildiv(NIMG, ROWSPB), 256, 0, st>>>(y2, 128);
        k_fuse<<<ceildiv(NIMG * HDIM, 256), 256, 0, st>>>(
            bn1g + s * HDIM, bn1b + s * HDIM, bn2g + s * HDIM, bn2b + s * HDIM, s);

        // fuse classifier
        k_gemm<128, 64, 8, 4, true><<<grid_big(NIMG, HIDD), 256, 0, st>>>(
            feats + s * HDIM, 2 * HDIM, wfa + (size_t)s * HDIM * HIDD, bfa + s * HIDD,
            H1, NIMG, HIDD, HDIM);
        k_gemm<64, 32, 4, 2, false><<<grid_small(NIMG, CDIM), 256, 0, st>>>(
            H1, HIDD, wfb + (size_t)s * HIDD * CDIM, bfb + s * CDIM, fpred, NIMG, CDIM, HIDD);

        // seg_loss(fuse_pred, img_label) * 0.5
        cudaMemsetAsync(p_gts, 0, CDIM * sizeof(int), st);
        k_hist<<<ceildiv(NIMG, 256), 256, 0, st>>>(img_label, NIMG);
        k_softmax_keys<<<ceildiv(NIMG, 256), 256, 0, st>>>(fpred, img_label, NIMG, 0.5f);
        run_lovasz(NIMG, 0.5f);

        // KL * 0.05/2 (mean over NIMG*C elements)
        k_kl<<<ceildiv(NIMG, 256), 256, 0, st>>>(0.025 / ((double)NIMG * (double)CDIM));
    }

    // final classifier on concatenated feats
    k_gemm<128, 64, 8, 4, true><<<grid_big(NIMG, HIDD), 256, 0, st>>>(
        feats, 2 * HDIM, clw1, clb1, H1, NIMG, HIDD, 2 * HDIM);
    k_gemm<64, 32, 4, 2, false><<<grid_small(NIMG, CDIM), 256, 0, st>>>(
        H1, HIDD, clw2, clb2, fpred, NIMG, CDIM, HIDD);
    cudaMemsetAsync(p_gts, 0, CDIM * sizeof(int), st);
    k_hist<<<ceildiv(NIMG, 256), 256, 0, st>>>(img_label, NIMG);
    k_softmax_keys<<<ceildiv(NIMG, 256), 256, 0, st>>>(fpred, img_label, NIMG, 1.0f);
    run_lovasz(NIMG, 1.0f);

    k_finish<<<1, 1, 0, st>>>((float*)d_out);
}

// round 4
// speedup vs baseline: 1.7264x; 1.4866x over previous
#include <cuda_runtime.h>
#include <cub/cub.cuh>
#include <math.h>
#include <stdint.h>

#define NSCALE 2
#define NPTS   240000
#define NVOX   80000
#define NPB    120000
#define MPB    30000
#define HDIM   64
#define CDIM   20
#define MIDD   16
#define HIDD   128
#define NIMG   60000
#define CUBTEMP_BYTES (32u*1024u*1024u)

// ------------------------- static device scratch (per-scale sets) -------------------------
__device__ float g_H1[NSCALE][(size_t)NVOX * HIDD];
__device__ float g_pred3d[NSCALE][(size_t)NVOX * CDIM];
__device__ int   g_counts[NSCALE][(size_t)NVOX * CDIM];
__device__ int   g_voxlab[NSCALE][NVOX];
__device__ int   g_idx[NSCALE][NIMG];
__device__ float g_P[NSCALE][(size_t)NIMG * HDIM];
__device__ float g_a1[NSCALE][(size_t)NIMG * MIDD];
__device__ float g_a2[NSCALE][(size_t)NIMG * MIDD];
__device__ float g_attw[NSCALE][(size_t)NIMG * 2];
__device__ float g_y1[NSCALE][(size_t)NIMG * HDIM];
__device__ float g_y2[NSCALE][(size_t)NIMG * HDIM];
__device__ float g_fpred[NSCALE][(size_t)NIMG * CDIM];
__device__ float g_stats[NSCALE][4 * HDIM];
__device__ uint32_t g_keys_in[NSCALE][(size_t)CDIM * NVOX];
__device__ uint32_t g_keys_out[NSCALE][(size_t)CDIM * NVOX];
__device__ int    g_gts_vox[NSCALE][CDIM];
__device__ double g_classLoss[NSCALE][CDIM];
__device__ unsigned char g_cubtemp[NSCALE][CUBTEMP_BYTES];
__device__ float g_feats[(size_t)NIMG * 2 * HDIM];   // disjoint column slices per scale
__device__ int    g_gts_img[CDIM];
__device__ double g_loss;

// ------------------------- reduction helper -------------------------
__device__ __forceinline__ double blockReduceSumD(double v) {
    __shared__ double sh[32];
    int lane = threadIdx.x & 31, wid = threadIdx.x >> 5;
#pragma unroll
    for (int o = 16; o > 0; o >>= 1) v += __shfl_down_sync(0xffffffffu, v, o);
    if (lane == 0) sh[wid] = v;
    __syncthreads();
    int nw = (blockDim.x + 31) >> 5;
    v = (threadIdx.x < nw) ? sh[threadIdx.x] : 0.0;
    if (wid == 0) {
#pragma unroll
        for (int o = 16; o > 0; o >>= 1) v += __shfl_down_sync(0xffffffffu, v, o);
    }
    return v;  // valid on thread 0
}

// ------------------------- elementwise kernels -------------------------
__global__ void k_scatter(const int* __restrict__ coors_s, const int* __restrict__ labels,
                          int* __restrict__ counts) {
    int i = blockIdx.x * blockDim.x + threadIdx.x;
    if (i < NPTS) atomicAdd(&counts[(size_t)coors_s[i] * CDIM + labels[i]], 1);
}

__global__ void k_argmax(const int* __restrict__ counts, int* __restrict__ voxlab,
                         int* __restrict__ gts) {
    __shared__ int h[CDIM];
    if (threadIdx.x < CDIM) h[threadIdx.x] = 0;
    __syncthreads();
    int v = blockIdx.x * blockDim.x + threadIdx.x;
    if (v < NVOX) {
        const int* row = counts + (size_t)v * CDIM;
        int best = row[0], bi = 0;
#pragma unroll
        for (int c = 1; c < CDIM; c++) { int x = row[c]; if (x > best) { best = x; bi = c; } }
        voxlab[v] = bi;
        atomicAdd(&h[bi], 1);
    }
    __syncthreads();
    if (threadIdx.x < CDIM && h[threadIdx.x]) atomicAdd(&gts[threadIdx.x], h[threadIdx.x]);
}

__global__ void k_hist(const int* __restrict__ lab, int n, int* __restrict__ gts) {
    __shared__ int h[CDIM];
    if (threadIdx.x < CDIM) h[threadIdx.x] = 0;
    __syncthreads();
    int i = blockIdx.x * blockDim.x + threadIdx.x;
    if (i < n) atomicAdd(&h[lab[i]], 1);
    __syncthreads();
    if (threadIdx.x < CDIM && h[threadIdx.x]) atomicAdd(&gts[threadIdx.x], h[threadIdx.x]);
}

__global__ void k_idxgather(const float* __restrict__ pts_s, const int* __restrict__ coors_s,
                            const int* __restrict__ p2img, int* __restrict__ idxArr,
                            float* __restrict__ P) {
    int t = blockIdx.x * blockDim.x + threadIdx.x;
    if (t < NIMG * HDIM) {
        int r = t >> 6, c = t & 63;
        int b = r / MPB;
        int vi = coors_s[b * NPB + p2img[r]];
        if (c == 0) idxArr[r] = vi;
        P[t] = pts_s[(size_t)vi * HDIM + c];
    }
}

__global__ void k_att(const float* __restrict__ a1, const float* __restrict__ a2,
                      float* __restrict__ attw,
                      const float* __restrict__ fc3w, const float* __restrict__ fc3b) {
    int r = blockIdx.x * blockDim.x + threadIdx.x;
    if (r >= NIMG) return;
    float z0 = fc3b[0], z1 = fc3b[1];
#pragma unroll
    for (int j = 0; j < MIDD; j++) {
        float v = a1[(size_t)r * MIDD + j];
        z0 += v * fc3w[j * 2 + 0];
        z1 += v * fc3w[j * 2 + 1];
    }
#pragma unroll
    for (int j = 0; j < MIDD; j++) {
        float v = a2[(size_t)r * MIDD + j];
        z0 += v * fc3w[(MIDD + j) * 2 + 0];
        z1 += v * fc3w[(MIDD + j) * 2 + 1];
    }
    attw[2 * r + 0] = 1.f / (1.f + expf(-z0));
    attw[2 * r + 1] = 1.f / (1.f + expf(-z1));
}

#define ROWSPB 512
__global__ void k_colstats(const float* __restrict__ y, float* __restrict__ stats, int statsOff) {
    const int col = threadIdx.x & 63;
    const int grp = threadIdx.x >> 6;  // 0..3
    float s = 0.f, q = 0.f;
    int r0 = blockIdx.x * ROWSPB;
    int rend = r0 + ROWSPB; if (rend > NIMG) rend = NIMG;
    for (int r = r0 + grp; r < rend; r += 4) {
        float v = y[(size_t)r * HDIM + col];
        s += v; q += v * v;
    }
    __shared__ float sh[2][4][64];
    sh[0][grp][col] = s; sh[1][grp][col] = q;
    __syncthreads();
    if (grp == 0) {
        s = sh[0][0][col] + sh[0][1][col] + sh[0][2][col] + sh[0][3][col];
        q = sh[1][0][col] + sh[1][1][col] + sh[1][2][col] + sh[1][3][col];
        atomicAdd(&stats[statsOff + col], s);
        atomicAdd(&stats[statsOff + 64 + col], q);
    }
}

__global__ void k_fuse(const float* __restrict__ y1, const float* __restrict__ y2,
                       const float* __restrict__ attw, const float* __restrict__ stats,
                       const float* __restrict__ g1, const float* __restrict__ b1,
                       const float* __restrict__ g2, const float* __restrict__ b2, int s) {
    int t = blockIdx.x * blockDim.x + threadIdx.x;
    if (t >= NIMG * HDIM) return;
    int r = t >> 6, c = t & 63;
    const float n = (float)NIMG;
    float mu1 = stats[c] / n;        float var1 = stats[64 + c] / n - mu1 * mu1;
    float mu2 = stats[128 + c] / n;  float var2 = stats[192 + c] / n - mu2 * mu2;
    float v1 = fmaxf((y1[t] - mu1) * rsqrtf(var1 + 1e-5f) * g1[c] + b1[c], 0.f);
    float v2 = fmaxf((y2[t] - mu2) * rsqrtf(var2 + 1e-5f) * g2[c] + b2[c], 0.f);
    g_feats[(size_t)r * (2 * HDIM) + s * HDIM + c] = v1 * attw[2 * r] + v2 * attw[2 * r + 1];
}

// ------------------------- big GEMM (f32x2): C = act(A[M,K] @ W[K,N] + bias) -------------------------
// requires N % BN == 0, K % 16 == 0, 16B-aligned A/W rows.
template <int BM, int BN, int TM, int TN, bool RELU>
__global__ void __launch_bounds__(256) k_gemm2(const float* __restrict__ A, int lda,
                                               const float* __restrict__ W,
                                               const float* __restrict__ bias,
                                               float* __restrict__ Cm,
                                               int M, int N, int K) {
    constexpr int TX = BN / TN;
    constexpr int TY = BM / TM;
    static_assert(TX * TY == 256 && TM == 8 && (TN == 4 || TN == 8), "bad tile");
    __shared__ __align__(16) float As[16][BM + 4];
    __shared__ __align__(16) float Ws[16][BN + 4];
    const int bm = blockIdx.y * BM, bn = blockIdx.x * BN;
    const int tid = threadIdx.x;
    const int tx = tid % TX, ty = tid / TX;
    unsigned long long acc[TM][TN / 2] = {};
    for (int k0 = 0; k0 < K; k0 += 16) {
#pragma unroll
        for (int it = 0; it < BM / 64; it++) {
            int g = tid + it * 256;
            int m = g >> 2, q = g & 3;
            int gm = bm + m;
            float4 v = make_float4(0.f, 0.f, 0.f, 0.f);
            if (gm < M) v = *(const float4*)&A[(size_t)gm * lda + k0 + 4 * q];
            As[4 * q + 0][m] = v.x; As[4 * q + 1][m] = v.y;
            As[4 * q + 2][m] = v.z; As[4 * q + 3][m] = v.w;
        }
#pragma unroll
        for (int it = 0; it < BN / 64; it++) {
            int g = tid + it * 256;
            int kk = g / (BN / 4), nq = g % (BN / 4);
            *(float4*)&Ws[kk][4 * nq] = *(const float4*)&W[(size_t)(k0 + kk) * N + bn + 4 * nq];
        }
        __syncthreads();
#pragma unroll
        for (int kk = 0; kk < 16; kk++) {
            float a[TM];
            *(float4*)&a[0] = *(const float4*)&As[kk][ty * TM];
            *(float4*)&a[4] = *(const float4*)&As[kk][ty * TM + 4];
            unsigned long long b2[TN / 2];
            *(ulonglong2*)&b2[0] = *(const ulonglong2*)&Ws[kk][tx * TN];
            if constexpr (TN == 8) {
                *(ulonglong2*)&b2[2] = *(const ulonglong2*)&Ws[kk][tx * TN + 4];
            }
#pragma unroll
            for (int i = 0; i < TM; i++) {
                unsigned long long a2;
                asm("mov.b64 %0, {%1, %1};" : "=l"(a2) : "f"(a[i]));
#pragma unroll
                for (int j = 0; j < TN / 2; j++)
                    asm("fma.rn.f32x2 %0, %1, %2, %0;" : "+l"(acc[i][j]) : "l"(a2), "l"(b2[j]));
            }
        }
        __syncthreads();
    }
#pragma unroll
    for (int i = 0; i < TM; i++) {
        int gm = bm + ty * TM + i;
        if (gm >= M) continue;
#pragma unroll
        for (int j = 0; j < TN / 2; j++) {
            int gn = bn + tx * TN + 2 * j;
            float lo = __uint_as_float((unsigned)(acc[i][j] & 0xFFFFFFFFull)) + bias[gn];
            float hi = __uint_as_float((unsigned)(acc[i][j] >> 32)) + bias[gn + 1];
            if (RELU) { lo = fmaxf(lo, 0.f); hi = fmaxf(hi, 0.f); }
            *(float2*)&Cm[(size_t)gm * N + gn] = make_float2(lo, hi);
        }
    }
}

// ------------------------- small-N GEMM (scalar) -------------------------
template <int BM, int BN, int TM, int TN, bool RELU>
__global__ void __launch_bounds__(256) k_gemm(const float* __restrict__ A, int lda,
                                              const float* __restrict__ W,
                                              const float* __restrict__ bias,
                                              float* __restrict__ Cm,
                                              int M, int N, int K) {
    constexpr int TX = BN / TN;
    constexpr int TY = BM / TM;
    static_assert(TX * TY == 256, "bad tile");
    __shared__ __align__(16) float As[16][BM + 4];
    __shared__ __align__(16) float Ws[16][BN + 4];
    const int bm = blockIdx.y * BM, bn = blockIdx.x * BN;
    const int tid = threadIdx.x;
    const int tx = tid % TX, ty = tid / TX;
    float acc[TM][TN] = {};
    for (int k0 = 0; k0 < K; k0 += 16) {
#pragma unroll
        for (int e = tid; e < BM * 16; e += 256) {
            int m = e >> 4, kk = e & 15;
            int gm = bm + m;
            As[kk][m] = (gm < M) ? A[(size_t)gm * lda + (k0 + kk)] : 0.f;
        }
#pragma unroll
        for (int e = tid; e < BN * 16; e += 256) {
            int kk = e / BN, n2 = e % BN;
            int gn = bn + n2;
            Ws[kk][n2] = (gn < N) ? W[(size_t)(k0 + kk) * N + gn] : 0.f;
        }
        __syncthreads();
#pragma unroll
        for (int kk = 0; kk < 16; kk++) {
            float a[TM], b[TN];
#pragma unroll
            for (int i = 0; i < TM; i++) a[i] = As[kk][ty * TM + i];
#pragma unroll
            for (int j = 0; j < TN; j++) b[j] = Ws[kk][tx * TN + j];
#pragma unroll
            for (int i = 0; i < TM; i++)
#pragma unroll
                for (int j = 0; j < TN; j++) acc[i][j] += a[i] * b[j];
        }
        __syncthreads();
    }
#pragma unroll
    for (int i = 0; i < TM; i++) {
        int gm = bm + ty * TM + i;
        if (gm >= M) continue;
#pragma unroll
        for (int j = 0; j < TN; j++) {
            int gn = bn + tx * TN + j;
            if (gn < N) {
                float v = acc[i][j] + bias[gn];
                if (RELU) v = fmaxf(v, 0.f);
                Cm[(size_t)gm * N + gn] = v;
            }
        }
    }
}

// ------------------------- loss kernels -------------------------
// per row: softmax, CE contribution, packed 32-bit lovasz sort keys
// key = (c << 26) | ((0x3F800000 - err_bits) >> 5 << 1) | fg
__global__ void k_softmax_keys(const float* __restrict__ logits, const int* __restrict__ lab,
                               int n, float ce_w, uint32_t* __restrict__ keys) {
    int i = blockIdx.x * blockDim.x + threadIdx.x;
    double ce = 0.0;
    if (i < n) {
        float z[CDIM];
#pragma unroll
        for (int c = 0; c < CDIM; c++) z[c] = logits[(size_t)i * CDIM + c];
        float m = z[0];
#pragma unroll
        for (int c = 1; c < CDIM; c++) m = fmaxf(m, z[c]);
        float se = 0.f;
#pragma unroll
        for (int c = 0; c < CDIM; c++) se += expf(z[c] - m);
        float ls = logf(se);
        int l = lab[i];
        ce = -(double)(z[l] - m - ls);
#pragma unroll
        for (int c = 0; c < CDIM; c++) {
            float p = expf(z[c] - m - ls);
            uint32_t fg = (c == l) ? 1u : 0u;
            float err = fabsf((float)fg - p);
            uint32_t desc = 0x3F800000u - __float_as_uint(err);
            keys[(size_t)c * n + i] = ((uint32_t)c << 26) | (((desc >> 5) << 1) | fg);
        }
    }
    double tot = blockReduceSumD(ce);
    if (threadIdx.x == 0) atomicAdd(&g_loss, tot * (double)ce_w / (double)n);
}

// one block per class over its sorted segment
__global__ void __launch_bounds__(1024) k_lovasz(const uint32_t* __restrict__ keysAll,
                                                 const int* __restrict__ gts,
                                                 double* __restrict__ classLoss, int n) {
    int c = blockIdx.x;
    int tid = threadIdx.x, lane = tid & 31, wid = tid >> 5;
    const uint32_t* keys = keysAll + (size_t)c * n;
    float g = (float)gts[c];
    __shared__ int shWs[32];
    __shared__ double shD[32];
    int carry = 0;
    double acc = 0.0;
    for (int pos0 = 0; pos0 < n; pos0 += 1024) {
        int pos = pos0 + tid;
        int f = 0; float e = 0.f;
        if (pos < n) {
            uint32_t k = keys[pos];
            f = (int)(k & 1u);
            uint32_t desc = (k >> 1) & 0x1FFFFFFu;
            e = __uint_as_float(0x3F800000u - (desc << 5));
        }
        unsigned bal = __ballot_sync(0xffffffffu, f);
        int inclw = __popc(bal & (0xFFFFFFFFu >> (31 - lane)));
        if (lane == 31) shWs[wid] = inclw;
        __syncthreads();
        if (wid == 0) {
            int v = shWs[lane];
#pragma unroll
            for (int o = 1; o < 32; o <<= 1) {
                int u = __shfl_up_sync(0xffffffffu, v, o);
                if (lane >= o) v += u;
            }
            shWs[lane] = v;
        }
        __syncthreads();
        int cf = carry + inclw + (wid > 0 ? shWs[wid - 1] : 0);
        int total = shWs[31];
        if (pos < n) {
            float fi = (float)pos + 1.f;
            float cff = (float)cf;
            float jac = 1.f - (g - cff) / (g + fi - cff);
            float jacp = 0.f;
            if (pos > 0) {
                float cfp = cff - (float)f;
                jacp = 1.f - (g - cfp) / (g + (fi - 1.f) - cfp);
            }
            acc += (double)(e * (jac - jacp));
        }
        carry += total;
        __syncthreads();
    }
#pragma unroll
    for (int o = 16; o > 0; o >>= 1) acc += __shfl_down_sync(0xffffffffu, acc, o);
    if (lane == 0) shD[wid] = acc;
    __syncthreads();
    if (wid == 0) {
        double v = shD[lane];
#pragma unroll
        for (int o = 16; o > 0; o >>= 1) v += __shfl_down_sync(0xffffffffu, v, o);
        if (tid == 0) classLoss[c] = v;
    }
}

__global__ void k_lovreduce(float w, const int* __restrict__ gts,
                            const double* __restrict__ classLoss) {
    int tid = threadIdx.x;
    double s = 0.0; int pc = 0;
    if (tid < CDIM && gts[tid] > 0) { s = classLoss[tid]; pc = 1; }
#pragma unroll
    for (int o = 16; o > 0; o >>= 1) {
        s += __shfl_down_sync(0xffffffffu, s, o);
        pc += __shfl_down_sync(0xffffffffu, pc, o);
    }
    if (tid == 0) {
        int d = pc > 0 ? pc : 1;
        atomicAdd(&g_loss, (double)w * s / (double)d);
    }
}

__global__ void k_kl(double w, const float* __restrict__ fpred,
                     const float* __restrict__ pred3d, const int* __restrict__ idxArr) {
    int r = blockIdx.x * blockDim.x + threadIdx.x;
    double local = 0.0;
    if (r < NIMG) {
        float zf[CDIM], zp[CDIM];
        int vi = idxArr[r];
#pragma unroll
        for (int c = 0; c < CDIM; c++) {
            zf[c] = fpred[(size_t)r * CDIM + c];
            zp[c] = pred3d[(size_t)vi * CDIM + c];
        }
        float mf = zf[0], mp = zp[0];
#pragma unroll
        for (int c = 1; c < CDIM; c++) { mf = fmaxf(mf, zf[c]); mp = fmaxf(mp, zp[c]); }
        float sf = 0.f, sp = 0.f;
#pragma unroll
        for (int c = 0; c < CDIM; c++) { sf += expf(zf[c] - mf); sp += expf(zp[c] - mp); }
        float lsf = logf(sf), lsp = logf(sp);
        float acc = 0.f;
#pragma unroll
        for (int c = 0; c < CDIM; c++) {
            float lp = zf[c] - mf - lsf;
            float p = expf(lp);
            float lq = zp[c] - mp - lsp;
            acc += p * (lp - lq);
        }
        local = (double)acc;
    }
    double tot = blockReduceSumD(local);
    if (threadIdx.x == 0) atomicAdd(&g_loss, tot * w);
}

__global__ void k_finish(float* out) { out[0] = (float)g_loss; }

// ------------------------- host -------------------------
static inline int ceildiv(int a, int b) { return (a + b - 1) / b; }

extern "C" void kernel_launch(void* const* d_in, const int* in_sizes, int n_in,
                              void* d_out, int out_size) {
    const float* img_feat = (const float*)d_in[0];
    const float* pts_feat = (const float*)d_in[1];
    const int*   coors_inv = (const int*)d_in[2];
    const int*   labels   = (const int*)d_in[3];
    const int*   img_label = (const int*)d_in[4];
    const int*   p2img    = (const int*)d_in[5];
    const float* w3a = (const float*)d_in[6];  const float* b3a = (const float*)d_in[7];
    const float* w3b = (const float*)d_in[8];  const float* b3b = (const float*)d_in[9];
    const float* wfa = (const float*)d_in[10]; const float* bfa = (const float*)d_in[11];
    const float* wfb = (const float*)d_in[12]; const float* bfb = (const float*)d_in[13];
    const float* fc1w = (const float*)d_in[14]; const float* fc1b = (const float*)d_in[15];
    const float* fc2w = (const float*)d_in[16]; const float* fc2b = (const float*)d_in[17];
    const float* fc3w = (const float*)d_in[18]; const float* fc3b = (const float*)d_in[19];
    const float* c1w = (const float*)d_in[20]; const float* c1b = (const float*)d_in[21];
    const float* bn1g = (const float*)d_in[22]; const float* bn1b = (const float*)d_in[23];
    const float* c2w = (const float*)d_in[24]; const float* c2b = (const float*)d_in[25];
    const float* bn2g = (const float*)d_in[26]; const float* bn2b = (const float*)d_in[27];
    const float* clw1 = (const float*)d_in[28]; const float* clb1 = (const float*)d_in[29];
    const float* clw2 = (const float*)d_in[30]; const float* clb2 = (const float*)d_in[31];

    // resolve static scratch
    void *pv;
    cudaGetSymbolAddress(&pv, g_H1);       float* H1b = (float*)pv;
    cudaGetSymbolAddress(&pv, g_pred3d);   float* predb = (float*)pv;
    cudaGetSymbolAddress(&pv, g_counts);   int* countsb = (int*)pv;
    cudaGetSymbolAddress(&pv, g_voxlab);   int* voxlabb = (int*)pv;
    cudaGetSymbolAddress(&pv, g_idx);      int* idxb = (int*)pv;
    cudaGetSymbolAddress(&pv, g_P);        float* Pb = (float*)pv;
    cudaGetSymbolAddress(&pv, g_a1);       float* a1b = (float*)pv;
    cudaGetSymbolAddress(&pv, g_a2);       float* a2b = (float*)pv;
    cudaGetSymbolAddress(&pv, g_attw);     float* attwb = (float*)pv;
    cudaGetSymbolAddress(&pv, g_y1);       float* y1b = (float*)pv;
    cudaGetSymbolAddress(&pv, g_y2);       float* y2b = (float*)pv;
    cudaGetSymbolAddress(&pv, g_fpred);    float* fpredb = (float*)pv;
    cudaGetSymbolAddress(&pv, g_stats);    float* statsb = (float*)pv;
    cudaGetSymbolAddress(&pv, g_keys_in);  uint32_t* kinb = (uint32_t*)pv;
    cudaGetSymbolAddress(&pv, g_keys_out); uint32_t* koutb = (uint32_t*)pv;
    cudaGetSymbolAddress(&pv, g_gts_vox);  int* gtsvoxb = (int*)pv;
    cudaGetSymbolAddress(&pv, g_classLoss);double* clsb = (double*)pv;
    cudaGetSymbolAddress(&pv, g_cubtemp);  unsigned char* tempb = (unsigned char*)pv;
    cudaGetSymbolAddress(&pv, g_feats);    float* feats = (float*)pv;
    cudaGetSymbolAddress(&pv, g_gts_img);  int* gtsimg = (int*)pv;
    cudaGetSymbolAddress(&pv, g_loss);     void* p_loss = pv;

    // lazily created streams/events (host resources only; created on the
    // uncaptured correctness call, reused during capture)
    static cudaStream_t strS[NSCALE] = {nullptr, nullptr};
    static cudaEvent_t evFork = nullptr, evJoin[NSCALE] = {nullptr, nullptr};
    if (!strS[0]) {
        for (int s = 0; s < NSCALE; s++) {
            cudaStreamCreateWithFlags(&strS[s], cudaStreamNonBlocking);
            cudaEventCreateWithFlags(&evJoin[s], cudaEventDisableTiming);
        }
        cudaEventCreateWithFlags(&evFork, cudaEventDisableTiming);
    }

    cudaStream_t st0 = 0;
    cudaMemsetAsync(p_loss, 0, sizeof(double), st0);
    cudaMemsetAsync(gtsimg, 0, CDIM * sizeof(int), st0);
    k_hist<<<ceildiv(NIMG, 256), 256, 0, st0>>>(img_label, NIMG, gtsimg);

    // fork
    cudaEventRecord(evFork, st0);
    for (int s = 0; s < NSCALE; s++) cudaStreamWaitEvent(strS[s], evFork, 0);

    auto run_lovasz = [&](int s, int n, float weight, const int* gts, cudaStream_t st) {
        uint32_t* kin = kinb + (size_t)s * CDIM * NVOX;
        uint32_t* kout = koutb + (size_t)s * CDIM * NVOX;
        double* cls = clsb + (size_t)s * CDIM;
        size_t tb = CUBTEMP_BYTES;
        cub::DeviceRadixSort::SortKeys(tempb + (size_t)s * CUBTEMP_BYTES, tb,
                                       kin, kout, CDIM * n, 0, 31, st);
        k_lovasz<<<CDIM, 1024, 0, st>>>(kout, gts, cls, n);
        k_lovreduce<<<1, 32, 0, st>>>(weight, gts, cls);
    };

    for (int s = 0; s < NSCALE; s++) {
        cudaStream_t st = strS[s];
        const float* pts_s = pts_feat + (size_t)s * NVOX * HDIM;
        const float* img_s = img_feat + (size_t)s * NIMG * HDIM;
        const int* coors_s = coors_inv + (size_t)s * NPTS;
        float* H1 = H1b + (size_t)s * NVOX * HIDD;
        float* pred = predb + (size_t)s * NVOX * CDIM;
        int* counts = countsb + (size_t)s * NVOX * CDIM;
        int* voxlab = voxlabb + (size_t)s * NVOX;
        int* idxArr = idxb + (size_t)s * NIMG;
        float* P = Pb + (size_t)s * NIMG * HDIM;
        float* a1 = a1b + (size_t)s * NIMG * MIDD;
        float* a2 = a2b + (size_t)s * NIMG * MIDD;
        float* attw = attwb + (size_t)s * NIMG * 2;
        float* y1 = y1b + (size_t)s * NIMG * HDIM;
        float* y2 = y2b + (size_t)s * NIMG * HDIM;
        float* fpred = fpredb + (size_t)s * NIMG * CDIM;
        float* stats = statsb + (size_t)s * 4 * HDIM;
        uint32_t* kin = kinb + (size_t)s * CDIM * NVOX;
        int* gtsvox = gtsvoxb + (size_t)s * CDIM;

        // 3D classifier: pred3d = relu(pts @ w3a + b3a) @ w3b + b3b
        k_gemm2<128, 128, 8, 8, true><<<dim3(1, ceildiv(NVOX, 128)), 256, 0, st>>>(
            pts_s, HDIM, w3a + (size_t)s * HDIM * HIDD, b3a + s * HIDD, H1, NVOX, HIDD, HDIM);
        k_gemm<64, 32, 4, 2, false><<<dim3(1, ceildiv(NVOX, 64)), 256, 0, st>>>(
            H1, HIDD, w3b + (size_t)s * HIDD * CDIM, b3b + s * CDIM, pred, NVOX, CDIM, HIDD);

        // voxel majority vote + hist
        cudaMemsetAsync(counts, 0, (size_t)NVOX * CDIM * sizeof(int), st);
        cudaMemsetAsync(gtsvox, 0, CDIM * sizeof(int), st);
        k_scatter<<<ceildiv(NPTS, 256), 256, 0, st>>>(coors_s, labels, counts);
        k_argmax<<<ceildiv(NVOX, 256), 256, 0, st>>>(counts, voxlab, gtsvox);

        // seg_loss(pred3d, vox_lab)
        k_softmax_keys<<<ceildiv(NVOX, 256), 256, 0, st>>>(pred, voxlab, NVOX, 1.0f, kin);
        run_lovasz(s, NVOX, 1.0f, gtsvox, st);

        // fusion path
        k_idxgather<<<ceildiv(NIMG * HDIM, 256), 256, 0, st>>>(pts_s, coors_s, p2img, idxArr, P);
        k_gemm<64, 32, 4, 2, false><<<dim3(1, ceildiv(NIMG, 64)), 256, 0, st>>>(
            P, HDIM, fc1w + (size_t)s * HDIM * MIDD, fc1b + s * MIDD, a1, NIMG, MIDD, HDIM);
        k_gemm<64, 32, 4, 2, false><<<dim3(1, ceildiv(NIMG, 64)), 256, 0, st>>>(
            img_s, HDIM, fc2w + (size_t)s * HDIM * MIDD, fc2b + s * MIDD, a2, NIMG, MIDD, HDIM);
        k_att<<<ceildiv(NIMG, 256), 256, 0, st>>>(a1, a2, attw,
            fc3w + (size_t)s * 2 * MIDD * 2, fc3b + s * 2);
        k_gemm2<128, 64, 8, 4, false><<<dim3(1, ceildiv(NIMG, 128)), 256, 0, st>>>(
            P, HDIM, c1w + (size_t)s * HDIM * HDIM, c1b + s * HDIM, y1, NIMG, HDIM, HDIM);
        k_gemm2<128, 64, 8, 4, false><<<dim3(1, ceildiv(NIMG, 128)), 256, 0, st>>>(
            img_s, HDIM, c2w + (size_t)s * HDIM * HDIM, c2b + s * HDIM, y2, NIMG, HDIM, HDIM);
        cudaMemsetAsync(stats, 0, 4 * HDIM * sizeof(float), st);
        k_colstats<<<ceildiv(NIMG, ROWSPB), 256, 0, st>>>(y1, stats, 0);
        k_colstats<<<ceildiv(NIMG, ROWSPB), 256, 0, st>>>(y2, stats, 128);
        k_fuse<<<ceildiv(NIMG * HDIM, 256), 256, 0, st>>>(y1, y2, attw, stats,
            bn1g + s * HDIM, bn1b + s * HDIM, bn2g + s * HDIM, bn2b + s * HDIM, s);

        // fuse classifier
        k_gemm2<128, 128, 8, 8, true><<<dim3(1, ceildiv(NIMG, 128)), 256, 0, st>>>(
            feats + s * HDIM, 2 * HDIM, wfa + (size_t)s * HDIM * HIDD, bfa + s * HIDD,
            H1, NIMG, HIDD, HDIM);
        k_gemm<64, 32, 4, 2, false><<<dim3(1, ceildiv(NIMG, 64)), 256, 0, st>>>(
            H1, HIDD, wfb + (size_t)s * HIDD * CDIM, bfb + s * CDIM, fpred, NIMG, CDIM, HIDD);

        // seg_loss(fuse_pred, img_label) * 0.5
        k_softmax_keys<<<ceildiv(NIMG, 256), 256, 0, st>>>(fpred, img_label, NIMG, 0.5f, kin);
        run_lovasz(s, NIMG, 0.5f, gtsimg, st);

        // KL * 0.05/2, mean over NIMG*C elements
        k_kl<<<ceildiv(NIMG, 256), 256, 0, st>>>(0.025 / ((double)NIMG * (double)CDIM),
                                                 fpred, pred, idxArr);
    }

    // join
    for (int s = 0; s < NSCALE; s++) {
        cudaEventRecord(evJoin[s], strS[s]);
        cudaStreamWaitEvent(st0, evJoin[s], 0);
    }

    // final classifier on concatenated feats (uses set-0 scratch)
    k_gemm2<128, 128, 8, 8, true><<<dim3(1, ceildiv(NIMG, 128)), 256, 0, st0>>>(
        feats, 2 * HDIM, clw1, clb1, H1b, NIMG, HIDD, 2 * HDIM);
    k_gemm<64, 32, 4, 2, false><<<dim3(1, ceildiv(NIMG, 64)), 256, 0, st0>>>(
        H1b, HIDD, clw2, clb2, fpredb, NIMG, CDIM, HIDD);
    k_softmax_keys<<<ceildiv(NIMG, 256), 256, 0, st0>>>(fpredb, img_label, NIMG, 1.0f, kinb);
    {
        size_t tb = CUBTEMP_BYTES;
        cub::DeviceRadixSort::SortKeys(tempb, tb, kinb, koutb, CDIM * NIMG, 0, 31, st0);
        k_lovasz<<<CDIM, 1024, 0, st0>>>(koutb, gtsimg, clsb, NIMG);
        k_lovreduce<<<1, 32, 0, st0>>>(1.0f, gtsimg, clsb);
    }

    k_finish<<<1, 1, 0, st0>>>((float*)d_out);
}